// round 8
// baseline (speedup 1.0000x reference)
#include <cuda_runtime.h>

// DockBoardAttention: B=65536 tiny attentions, 2 warps per batch.
// Precompute (prep kernel):
//   W1[m][c] = 0.25 * sum_d Wq[d][m] * Wk[d][c]      (25x32, includes 1/sqrt(HD))
//   b1[c]    = 0.25 * sum_d bq[d]    * Wk[d][c]
//   W2[e][c] = sum_d Wo[e][d] * Wv[d][c]             (16x32)
//   b2[e]    = sum_d Wo[e][d] * bv[d] + bo[e]
// Per batch (pair of warps, warp h owns s = 32h + lane):
//   QWk[n][c] = dock[n][:] @ W1 + b1                 (computed redundantly per warp)
//   logit[s]  = sum_c QWk[n][c] * g[c][s]            (1 per lane)
//   softmax over 64 s: warp reduce + named-barrier pair exchange
//     (smax / ssum are DISJOINT buffers: every same-array write->read pair is
//      barrier-separated, killing the WAR race the single-buffer version had)
//   AG_h[n][c] = sum_{s in half} attn[s] * g[c][s]   (butterfly shuffle reduce)
//   out[n][e] = sum_c W2[e][c] * (AG_0+AG_1)[n][c] + b2[e]   (warp h=0)

#define NDOCK 3
#define DCELL 25
#define CCH   32
#define HW    64
#define HD    16
#define BPB   4      // batches (pairs) per block; block = 256 threads

__device__ float g_W1[DCELL * CCH];
__device__ float g_b1[CCH];
__device__ float g_W2[HD * CCH];
__device__ float g_b2[HD];

__global__ void prep_kernel(const float* __restrict__ Wq, const float* __restrict__ bq,
                            const float* __restrict__ Wk,
                            const float* __restrict__ Wv, const float* __restrict__ bv,
                            const float* __restrict__ Wo, const float* __restrict__ bo) {
    int t = threadIdx.x;
    if (t < DCELL * CCH) {
        int m = t / CCH, c = t % CCH;
        float s = 0.f;
        #pragma unroll
        for (int d = 0; d < HD; d++) s += Wq[d * DCELL + m] * Wk[d * CCH + c];
        g_W1[t] = 0.25f * s;
    }
    if (t < CCH) {
        float s = 0.f;
        #pragma unroll
        for (int d = 0; d < HD; d++) s += bq[d] * Wk[d * CCH + t];
        g_b1[t] = 0.25f * s;
    }
    if (t < HD * CCH) {
        int e = t / CCH, c = t % CCH;
        float s = 0.f;
        #pragma unroll
        for (int d = 0; d < HD; d++) s += Wo[e * HD + d] * Wv[d * CCH + c];
        g_W2[t] = s;
    }
    if (t < HD) {
        float s = bo[t];
        #pragma unroll
        for (int d = 0; d < HD; d++) s += Wo[t * HD + d] * bv[d];
        g_b2[t] = s;
    }
}

// Named barrier across the 2 warps (64 threads) of one batch-pair.
#define PAIR_BAR() asm volatile("bar.sync %0, 64;" :: "r"(pair + 1) : "memory")

// Butterfly exchange-reduce stage: halves the owned-channel set per stage.
#define XSTAGE(o, hh)                                                       \
    {                                                                       \
        const bool hi_ = (l & (o)) != 0;                                    \
        _Pragma("unroll")                                                   \
        for (int i_ = 0; i_ < (hh); i_++) {                                 \
            float send_ = hi_ ? A[i_] : A[i_ + (hh)];                       \
            float recv_ = __shfl_xor_sync(0xffffffffu, send_, (o));         \
            float keep_ = hi_ ? A[i_ + (hh)] : A[i_];                       \
            A[i_] = keep_ + recv_;                                          \
        }                                                                   \
    }

__global__ __launch_bounds__(256, 4) void dock_attn_kernel(
    const float* __restrict__ dock, const float* __restrict__ grid,
    float* __restrict__ out, int nbatch)
{
    __shared__ float sW1[DCELL * 32];       // [m][c] pitch 32
    __shared__ float sb1[32];
    __shared__ float sW2[HD * 36];          // [e][c] pitch 36
    __shared__ float sb2[HD];
    __shared__ float sdock[BPB][3 * 28];    // per pair, rows pitch 28
    __shared__ float sqwk[8][3 * 32];       // per WARP private QWk copy
    __shared__ float sagp[BPB][2][3 * 32];  // per pair, per half: AG partials
    __shared__ float smax[BPB][2];          // softmax exchange: max
    __shared__ float ssum[BPB][2];          // softmax exchange: sum (disjoint!)

    const int tid  = threadIdx.x;
    const int wid  = tid >> 5;
    const int pair = tid >> 6;              // 0..3
    const int h    = (tid >> 5) & 1;        // s-half
    const int l    = tid & 31;
    int b = blockIdx.x * BPB + pair;
    if (b >= nbatch) b = nbatch - 1;        // duplicate work, identical writes

    // ---- weights -> shared ----
    for (int i = tid; i < DCELL * 32; i += 256) sW1[i] = g_W1[i];
    for (int i = tid; i < HD * 32; i += 256)
        sW2[(i >> 5) * 36 + (i & 31)] = g_W2[i];
    if (tid < 32) sb1[tid] = g_b1[tid];
    if (tid < HD) sb2[tid] = g_b2[tid];

    // ---- g half-tile -> registers: lane owns s = 32h + l, all 32 channels ----
    const float* gp = grid + (size_t)b * (CCH * HW) + (h << 5) + l;
    float G[32];
    #pragma unroll
    for (int c = 0; c < 32; c++) G[c] = __ldcs(gp + c * HW);

    // ---- dock -> shared (h=0 warp only) ----
    if (h == 0) {
        const float* dp = dock + (size_t)b * (NDOCK * DCELL);
        float v0 = __ldcs(dp + l);
        float v1 = __ldcs(dp + 32 + l);
        int i0 = l, i1 = 32 + l;
        sdock[pair][(i0 / 25) * 28 + (i0 % 25)] = v0;
        sdock[pair][(i1 / 25) * 28 + (i1 % 25)] = v1;
        if (l < 11) {
            float v2 = __ldcs(dp + 64 + l);
            int i2 = 64 + l;
            sdock[pair][(i2 / 25) * 28 + (i2 % 25)] = v2;
        }
    }
    __syncthreads();

    // ---- QWk[n][c=l] = dock[n][:] @ W1[:,l] + b1[l]  (redundant per warp) ----
    float q0 = sb1[l], q1 = q0, q2 = q0;
    #pragma unroll
    for (int m4 = 0; m4 < 24; m4 += 4) {
        const float4 a0 = *(const float4*)&sdock[pair][m4];
        const float4 a1 = *(const float4*)&sdock[pair][28 + m4];
        const float4 a2 = *(const float4*)&sdock[pair][56 + m4];
        float w0 = sW1[(m4 + 0) * 32 + l];
        float w1 = sW1[(m4 + 1) * 32 + l];
        float w2 = sW1[(m4 + 2) * 32 + l];
        float w3 = sW1[(m4 + 3) * 32 + l];
        q0 = fmaf(a0.x, w0, q0); q0 = fmaf(a0.y, w1, q0);
        q0 = fmaf(a0.z, w2, q0); q0 = fmaf(a0.w, w3, q0);
        q1 = fmaf(a1.x, w0, q1); q1 = fmaf(a1.y, w1, q1);
        q1 = fmaf(a1.z, w2, q1); q1 = fmaf(a1.w, w3, q1);
        q2 = fmaf(a2.x, w0, q2); q2 = fmaf(a2.y, w1, q2);
        q2 = fmaf(a2.z, w2, q2); q2 = fmaf(a2.w, w3, q2);
    }
    {
        float w0 = sW1[24 * 32 + l];
        q0 = fmaf(sdock[pair][24], w0, q0);
        q1 = fmaf(sdock[pair][28 + 24], w0, q1);
        q2 = fmaf(sdock[pair][56 + 24], w0, q2);
    }
    sqwk[wid][l] = q0; sqwk[wid][32 + l] = q1; sqwk[wid][64 + l] = q2;
    __syncwarp();

    // ---- per-n: logit -> softmax (cross-warp) -> butterfly AG partial ----
    #pragma unroll
    for (int n = 0; n < 3; n++) {
        float a = 0.f;
        #pragma unroll
        for (int c4 = 0; c4 < 32; c4 += 4) {
            const float4 qq = *(const float4*)&sqwk[wid][n * 32 + c4];
            a = fmaf(qq.x, G[c4 + 0], a);
            a = fmaf(qq.y, G[c4 + 1], a);
            a = fmaf(qq.z, G[c4 + 2], a);
            a = fmaf(qq.w, G[c4 + 3], a);
        }
        // max over 64 s: warp reduce + pair exchange (into smax)
        float mx = a;
        #pragma unroll
        for (int o = 16; o > 0; o >>= 1)
            mx = fmaxf(mx, __shfl_xor_sync(0xffffffffu, mx, o));
        if (l == 0) smax[pair][h] = mx;
        PAIR_BAR();
        mx = fmaxf(smax[pair][0], smax[pair][1]);
        float e = __expf(a - mx);
        float sm = e;
        #pragma unroll
        for (int o = 16; o > 0; o >>= 1)
            sm += __shfl_xor_sync(0xffffffffu, sm, o);
        if (l == 0) ssum[pair][h] = sm;    // disjoint array: no WAR with smax reads
        PAIR_BAR();
        float ex = e * __fdividef(1.f, ssum[pair][0] + ssum[pair][1]);

        // Butterfly: after 5 xor stages lane l holds AG_h[n][c=l].
        // Stage 1 (o=16) fused with the P computation: liveness capped at A[16].
        float A[16];
        {
            const bool hi_ = (l & 16) != 0;
            #pragma unroll
            for (int i = 0; i < 16; i++) {
                float Pl = ex * G[i];
                float Ph = ex * G[i + 16];
                float send_ = hi_ ? Pl : Ph;
                float recv_ = __shfl_xor_sync(0xffffffffu, send_, 16);
                float keep_ = hi_ ? Ph : Pl;
                A[i] = keep_ + recv_;
            }
        }
        XSTAGE(8, 8)
        XSTAGE(4, 4)
        XSTAGE(2, 2)
        XSTAGE(1, 1)
        sagp[pair][h][n * 32 + l] = A[0];
    }
    PAIR_BAR();

    // ---- out[n][e] = W2[e][:] . (AG0+AG1)[n][:] + b2[e]  (warp h=0) ----
    // lane l -> j1 = l (n = l>>4, e = l&15); lanes 0..15 also j2 = 32+l (n=2, e=l)
    if (h == 0) {
        const int n1 = l >> 4, e1 = l & 15;
        float o1 = sb2[e1];
        float o2 = sb2[e1];                 // lanes >=16: unused
        const float* w2r = &sW2[e1 * 36];
        const float* g0  = &sagp[pair][0][n1 * 32];
        const float* g1  = &sagp[pair][1][n1 * 32];
        const float* h0  = &sagp[pair][0][2 * 32];
        const float* h1  = &sagp[pair][1][2 * 32];
        #pragma unroll
        for (int c4 = 0; c4 < 32; c4 += 4) {
            const float4 wv = *(const float4*)(w2r + c4);
            const float4 p0 = *(const float4*)(g0 + c4);
            const float4 p1 = *(const float4*)(g1 + c4);
            const float4 r0 = *(const float4*)(h0 + c4);
            const float4 r1 = *(const float4*)(h1 + c4);
            o1 = fmaf(wv.x, p0.x + p1.x, o1);
            o1 = fmaf(wv.y, p0.y + p1.y, o1);
            o1 = fmaf(wv.z, p0.z + p1.z, o1);
            o1 = fmaf(wv.w, p0.w + p1.w, o1);
            o2 = fmaf(wv.x, r0.x + r1.x, o2);
            o2 = fmaf(wv.y, r0.y + r1.y, o2);
            o2 = fmaf(wv.z, r0.z + r1.z, o2);
            o2 = fmaf(wv.w, r0.w + r1.w, o2);
        }
        float* op = out + (size_t)b * (NDOCK * HD);
        op[l] = o1;
        if (l < 16) op[32 + l] = o2;
    }
}

extern "C" void kernel_launch(void* const* d_in, const int* in_sizes, int n_in,
                              void* d_out, int out_size) {
    const float* dock = (const float*)d_in[0];
    const float* grid = (const float*)d_in[1];
    const float* Wq   = (const float*)d_in[2];
    const float* bq   = (const float*)d_in[3];
    const float* Wk   = (const float*)d_in[4];
    // d_in[5] = bk: softmax-invariant, unused
    const float* Wv   = (const float*)d_in[6];
    const float* bv   = (const float*)d_in[7];
    const float* Wo   = (const float*)d_in[8];
    const float* bo   = (const float*)d_in[9];
    float* out = (float*)d_out;

    int nbatch = in_sizes[0] / (NDOCK * DCELL);

    prep_kernel<<<1, DCELL * CCH>>>(Wq, bq, Wk, Wv, bv, Wo, bo);
    int nblocks = (nbatch + BPB - 1) / BPB;
    dock_attn_kernel<<<nblocks, 256>>>(dock, grid, out, nbatch);
}

// round 10
// speedup vs baseline: 1.5045x; 1.5045x over previous
#include <cuda_runtime.h>

// DockBoardAttention: B=65536 tiny attentions. Persistent warps + L2 prefetch.
// Precompute (prep kernel):
//   W1[m][c] = 0.25 * sum_d Wq[d][m] * Wk[d][c]      (25x32, includes 1/sqrt(HD))
//   b1[c]    = 0.25 * sum_d bq[d]    * Wk[d][c]
//   W2[e][c] = sum_d Wo[e][d] * Wv[d][c]             (16x32)
//   b2[e]    = sum_d Wo[e][d] * bv[d] + bo[e]
// Per batch (one warp, grid-stride loop):
//   QWk[n][c] = dock[n][:] @ W1 + b1                 (bk drops out of softmax)
//   logits[n][s] = sum_c QWk[n][c] * g[c][s]
//   attn = softmax over s (64; 2 s per lane)
//   AG[n][c] = sum_s attn[n][s] * g[c][s]            (butterfly shuffle reduce)
//   out[n][e] = sum_c W2[e][c] * AG[n][c] + b2[e]
// Latency plan: each warp prefetches (prefetch.global.L2) the g-tile of the
// batch it will process 2 iterations from now; the actual LDGs then hit L2.

#define NDOCK 3
#define DCELL 25
#define CCH   32
#define HW    64
#define HD    16
#define WPB   4      // warps per block
#define NBLK  760    // 152 SM * 5 resident blocks -> 1 balanced wave

__device__ float g_W1[DCELL * CCH];
__device__ float g_b1[CCH];
__device__ float g_W2[HD * CCH];
__device__ float g_b2[HD];

__global__ void prep_kernel(const float* __restrict__ Wq, const float* __restrict__ bq,
                            const float* __restrict__ Wk,
                            const float* __restrict__ Wv, const float* __restrict__ bv,
                            const float* __restrict__ Wo, const float* __restrict__ bo) {
    int t = threadIdx.x;
    if (t < DCELL * CCH) {
        int m = t / CCH, c = t % CCH;
        float s = 0.f;
        #pragma unroll
        for (int d = 0; d < HD; d++) s += Wq[d * DCELL + m] * Wk[d * CCH + c];
        g_W1[t] = 0.25f * s;
    }
    if (t < CCH) {
        float s = 0.f;
        #pragma unroll
        for (int d = 0; d < HD; d++) s += bq[d] * Wk[d * CCH + t];
        g_b1[t] = 0.25f * s;
    }
    if (t < HD * CCH) {
        int e = t / CCH, c = t % CCH;
        float s = 0.f;
        #pragma unroll
        for (int d = 0; d < HD; d++) s += Wo[e * HD + d] * Wv[d * CCH + c];
        g_W2[t] = s;
    }
    if (t < HD) {
        float s = bo[t];
        #pragma unroll
        for (int d = 0; d < HD; d++) s += Wo[t * HD + d] * bv[d];
        g_b2[t] = s;
    }
}

// Butterfly exchange-reduce stage: halves the owned-channel set per stage.
#define XSTAGE(o, h)                                                        \
    {                                                                       \
        const bool hi_ = (l & (o)) != 0;                                    \
        _Pragma("unroll")                                                   \
        for (int i_ = 0; i_ < (h); i_++) {                                  \
            float send_ = hi_ ? A[i_] : A[i_ + (h)];                        \
            float recv_ = __shfl_xor_sync(0xffffffffu, send_, (o));         \
            float keep_ = hi_ ? A[i_ + (h)] : A[i_];                        \
            A[i_] = keep_ + recv_;                                          \
        }                                                                   \
    }

__global__ __launch_bounds__(WPB * 32, 5) void dock_attn_kernel(
    const float* __restrict__ dock, const float* __restrict__ grid,
    float* __restrict__ out, int nbatch)
{
    __shared__ float sW1[DCELL * 32];      // [m][c] pitch 32
    __shared__ float sb1[32];
    __shared__ float sW2[HD * 36];         // [e][c] pitch 36 (16B aligned rows)
    __shared__ float sb2[HD];
    __shared__ float sdock[WPB][3 * 28];   // 3 rows pitch 28 (float4-friendly)
    __shared__ float sqwk[WPB][3 * 32];
    __shared__ float sag [WPB][3 * 36];

    const int tid = threadIdx.x;
    const int w = tid >> 5, l = tid & 31;

    // ---- weights -> shared, once per block lifetime ----
    for (int i = tid; i < DCELL * 32; i += WPB * 32) sW1[i] = g_W1[i];
    for (int i = tid; i < HD * 32; i += WPB * 32)
        sW2[(i >> 5) * 36 + (i & 31)] = g_W2[i];
    if (tid < 32) sb1[tid] = g_b1[tid];
    if (tid < HD) sb2[tid] = g_b2[tid];
    __syncthreads();

    const int stride = gridDim.x * WPB;

    for (int b = blockIdx.x * WPB + w; b < nbatch; b += stride) {

        // ---- L2 prefetch of the g-tile we'll process 2 iterations from now ----
        {
            int pb = b + 2 * stride;
            if (pb < nbatch) {
                const float* pf = grid + (size_t)pb * (CCH * HW) + (l << 5);
                asm volatile("prefetch.global.L2 [%0];" :: "l"(pf));
                asm volatile("prefetch.global.L2 [%0];" :: "l"(pf + 1024));
            }
        }

        // ---- g tile -> registers: lane owns s = 2l, 2l+1 for all 32 channels ----
        const float2* gp = reinterpret_cast<const float2*>(grid + (size_t)b * (CCH * HW)) + l;
        float2 G[32];
        #pragma unroll
        for (int c = 0; c < 32; c++) G[c] = __ldcs(gp + c * 32);

        // ---- dock -> shared (padded rows of 28); warp-private buffer ----
        {
            const float* dp = dock + (size_t)b * (NDOCK * DCELL);
            float v0 = __ldcs(dp + l);
            float v1 = __ldcs(dp + 32 + l);
            int i0 = l, i1 = 32 + l;
            sdock[w][(i0 / 25) * 28 + (i0 % 25)] = v0;
            sdock[w][(i1 / 25) * 28 + (i1 % 25)] = v1;
            if (l < 11) {
                float v2 = __ldcs(dp + 64 + l);
                int i2 = 64 + l;
                sdock[w][(i2 / 25) * 28 + (i2 % 25)] = v2;
            }
        }
        __syncwarp();

        // ---- QWk[n][c=l] = dock[n][:] @ W1[:,l] + b1[l] ----
        float q0 = sb1[l], q1 = q0, q2 = q0;
        #pragma unroll
        for (int m4 = 0; m4 < 24; m4 += 4) {
            const float4 a0 = *(const float4*)&sdock[w][m4];
            const float4 a1 = *(const float4*)&sdock[w][28 + m4];
            const float4 a2 = *(const float4*)&sdock[w][56 + m4];
            float w0 = sW1[(m4 + 0) * 32 + l];
            float w1 = sW1[(m4 + 1) * 32 + l];
            float w2 = sW1[(m4 + 2) * 32 + l];
            float w3 = sW1[(m4 + 3) * 32 + l];
            q0 = fmaf(a0.x, w0, q0); q0 = fmaf(a0.y, w1, q0);
            q0 = fmaf(a0.z, w2, q0); q0 = fmaf(a0.w, w3, q0);
            q1 = fmaf(a1.x, w0, q1); q1 = fmaf(a1.y, w1, q1);
            q1 = fmaf(a1.z, w2, q1); q1 = fmaf(a1.w, w3, q1);
            q2 = fmaf(a2.x, w0, q2); q2 = fmaf(a2.y, w1, q2);
            q2 = fmaf(a2.z, w2, q2); q2 = fmaf(a2.w, w3, q2);
        }
        {
            float w0 = sW1[24 * 32 + l];
            q0 = fmaf(sdock[w][24], w0, q0);
            q1 = fmaf(sdock[w][28 + 24], w0, q1);
            q2 = fmaf(sdock[w][56 + 24], w0, q2);
        }
        sqwk[w][l] = q0; sqwk[w][32 + l] = q1; sqwk[w][64 + l] = q2;
        __syncwarp();

        // ---- per-n: logits -> softmax -> butterfly AG ----
        #pragma unroll
        for (int n = 0; n < 3; n++) {
            float ax = 0.f, ay = 0.f;
            #pragma unroll
            for (int c4 = 0; c4 < 32; c4 += 4) {
                const float4 qq = *(const float4*)&sqwk[w][n * 32 + c4];
                ax = fmaf(qq.x, G[c4 + 0].x, ax); ay = fmaf(qq.x, G[c4 + 0].y, ay);
                ax = fmaf(qq.y, G[c4 + 1].x, ax); ay = fmaf(qq.y, G[c4 + 1].y, ay);
                ax = fmaf(qq.z, G[c4 + 2].x, ax); ay = fmaf(qq.z, G[c4 + 2].y, ay);
                ax = fmaf(qq.w, G[c4 + 3].x, ax); ay = fmaf(qq.w, G[c4 + 3].y, ay);
            }
            // softmax over the 64 s values (2 per lane)
            float mx = fmaxf(ax, ay);
            #pragma unroll
            for (int o = 16; o > 0; o >>= 1)
                mx = fmaxf(mx, __shfl_xor_sync(0xffffffffu, mx, o));
            float ex = __expf(ax - mx), ey = __expf(ay - mx);
            float sm = ex + ey;
            #pragma unroll
            for (int o = 16; o > 0; o >>= 1)
                sm += __shfl_xor_sync(0xffffffffu, sm, o);
            float inv = __fdividef(1.f, sm);
            ex *= inv; ey *= inv;

            // Butterfly: after 5 xor stages lane l holds AG[n][c=l].
            // Stage 1 (o=16) fused with P computation: liveness capped at A[16].
            float A[16];
            {
                const bool hi_ = (l & 16) != 0;
                #pragma unroll
                for (int i = 0; i < 16; i++) {
                    float Pl = fmaf(ex, G[i].x,      ey * G[i].y);
                    float Ph = fmaf(ex, G[i + 16].x, ey * G[i + 16].y);
                    float send_ = hi_ ? Pl : Ph;
                    float recv_ = __shfl_xor_sync(0xffffffffu, send_, 16);
                    float keep_ = hi_ ? Ph : Pl;
                    A[i] = keep_ + recv_;
                }
            }
            XSTAGE(8, 8)
            XSTAGE(4, 4)
            XSTAGE(2, 2)
            XSTAGE(1, 1)
            sag[w][n * 36 + l] = A[0];
        }
        __syncwarp();

        // ---- out[n][e] = W2[e][:] . AG[n][:] + b2[e] ----
        // lane l -> j1 = l (n = l>>4, e = l&15); lanes 0..15 also j2 = 32+l (n=2, e=l)
        {
            const int n1 = l >> 4, e1 = l & 15;
            float o1 = sb2[e1];
            float o2 = sb2[e1];                 // lanes >=16: unused
            const float* w2r = &sW2[e1 * 36];
            const float* ag1 = &sag[w][n1 * 36];
            const float* ag2 = &sag[w][2 * 36];
            #pragma unroll
            for (int c4 = 0; c4 < 32; c4 += 4) {
                const float4 wv = *(const float4*)(w2r + c4);
                const float4 a1 = *(const float4*)(ag1 + c4);
                const float4 a2 = *(const float4*)(ag2 + c4);
                o1 = fmaf(wv.x, a1.x, o1); o1 = fmaf(wv.y, a1.y, o1);
                o1 = fmaf(wv.z, a1.z, o1); o1 = fmaf(wv.w, a1.w, o1);
                o2 = fmaf(wv.x, a2.x, o2); o2 = fmaf(wv.y, a2.y, o2);
                o2 = fmaf(wv.z, a2.z, o2); o2 = fmaf(wv.w, a2.w, o2);
            }
            float* op = out + (size_t)b * (NDOCK * HD);
            op[l] = o1;
            if (l < 16) op[32 + l] = o2;
        }
        __syncwarp();   // order this iter's sag/sqwk/sdock reads before next iter's writes
    }
}

extern "C" void kernel_launch(void* const* d_in, const int* in_sizes, int n_in,
                              void* d_out, int out_size) {
    const float* dock = (const float*)d_in[0];
    const float* grid = (const float*)d_in[1];
    const float* Wq   = (const float*)d_in[2];
    const float* bq   = (const float*)d_in[3];
    const float* Wk   = (const float*)d_in[4];
    // d_in[5] = bk: softmax-invariant, unused
    const float* Wv   = (const float*)d_in[6];
    const float* bv   = (const float*)d_in[7];
    const float* Wo   = (const float*)d_in[8];
    const float* bo   = (const float*)d_in[9];
    float* out = (float*)d_out;

    int nbatch = in_sizes[0] / (NDOCK * DCELL);

    prep_kernel<<<1, DCELL * CCH>>>(Wq, bq, Wk, Wv, bv, Wo, bo);
    dock_attn_kernel<<<NBLK, WPB * 32>>>(dock, grid, out, nbatch);
}